// round 1
// baseline (speedup 1.0000x reference)
#include <cuda_runtime.h>
#include <stdint.h>

// Problem constants (fixed by the reference).
#define NPRE     6000
#define NPOST    2000
#define IOU_THRF 0.7f
#define NB       94          // ceil(NPRE/64)
#define NROWS    (NB * 64)   // 6016, padded
#define HB       32768       // score histogram buckets (scores in [0,1))
#define CAND_MAX 8192        // candidate capacity for the top-k sort

// ---------------- persistent device scratch (no allocations allowed) --------
__device__ unsigned           g_hist[HB];
__device__ int                g_ncand;
__device__ int                g_thresh;
__device__ unsigned long long g_cand[CAND_MAX];
__device__ float              g_boxes[NROWS * 4];   // rows >= NPRE stay 0 forever
__device__ float              g_scores[NROWS];
__device__ unsigned long long g_mask[(size_t)NROWS * NB];

// ---------------- K1: zero histogram + counter ------------------------------
__global__ void zero_k() {
    int i = blockIdx.x * blockDim.x + threadIdx.x;
    if (i < HB) g_hist[i] = 0u;
    if (i == 0) g_ncand = 0;
}

// ---------------- K2: histogram of scores (monotone linear bucketing) -------
__global__ void hist_k(const float* __restrict__ scores, int n) {
    int i = blockIdx.x * blockDim.x + threadIdx.x;
    int stride = gridDim.x * blockDim.x;
    for (; i < n; i += stride) {
        float s = scores[i];
        int b = (int)(s * 32768.0f);
        b = max(0, min(HB - 1, b));
        atomicAdd(&g_hist[b], 1u);
    }
}

// ---------------- K3: find threshold bucket (descending suffix scan) --------
__global__ void thresh_k() {
    __shared__ unsigned s[1024];
    int t = threadIdx.x;
    int lo = HB - (t + 1) * 32;  // this thread owns buckets [lo, lo+32), t=0 is the top chunk
    unsigned sum = 0;
#pragma unroll
    for (int b = 0; b < 32; b++) sum += g_hist[lo + b];
    s[t] = sum;
    __syncthreads();
    // inclusive Hillis-Steele scan over descending chunks
    for (int off = 1; off < 1024; off <<= 1) {
        unsigned v = (t >= off) ? s[t - off] : 0u;
        __syncthreads();
        s[t] += v;
        __syncthreads();
    }
    unsigned incl = s[t];
    unsigned excl = incl - sum;
    if (excl < (unsigned)NPRE && incl >= (unsigned)NPRE) {
        unsigned cum = excl;
        for (int b = lo + 31; b >= lo; --b) {
            cum += g_hist[b];
            if (cum >= (unsigned)NPRE) { g_thresh = b; break; }
        }
    }
    if (t == 1023 && s[1023] < (unsigned)NPRE) g_thresh = 0;  // degenerate: take all
}

// ---------------- K4: compact candidate (score,index) keys ------------------
__global__ void compact_k(const float* __restrict__ scores, int n) {
    int T = g_thresh;
    int i = blockIdx.x * blockDim.x + threadIdx.x;
    int stride = gridDim.x * blockDim.x;
    for (; i < n; i += stride) {
        float s = scores[i];
        int b = (int)(s * 32768.0f);
        b = max(0, min(HB - 1, b));
        if (b >= T) {
            int p = atomicAdd(&g_ncand, 1);
            if (p < CAND_MAX) {
                // key: higher score first; ties -> lower index first
                g_cand[p] = ((unsigned long long)__float_as_uint(s) << 32)
                          | (unsigned long long)(0xFFFFFFFFu - (unsigned)i);
            }
        }
    }
}

// ---------------- K5: bitonic sort (descending) + gather + decode -----------
__global__ void sort_decode_k(const float* __restrict__ enc,
                              const float* __restrict__ anch, int n) {
    extern __shared__ unsigned long long sk[];
    int t = threadIdx.x, T = blockDim.x;
    int nc = g_ncand;
    if (nc > CAND_MAX) nc = CAND_MAX;
    for (int i = t; i < CAND_MAX; i += T) sk[i] = (i < nc) ? g_cand[i] : 0ull;
    __syncthreads();
    for (int k = 2; k <= CAND_MAX; k <<= 1) {
        for (int j = k >> 1; j > 0; j >>= 1) {
            for (int i = t; i < CAND_MAX; i += T) {
                int ixj = i ^ j;
                if (ixj > i) {
                    unsigned long long a = sk[i], b = sk[ixj];
                    bool descBlock = ((i & k) == 0);
                    if (descBlock ? (a < b) : (a > b)) { sk[i] = b; sk[ixj] = a; }
                }
            }
            __syncthreads();
        }
    }
    // decode top NPRE boxes (exactly the reference math)
    const float4* enc4  = (const float4*)enc;
    const float4* anch4 = (const float4*)anch;
    for (int r = t; r < NPRE; r += T) {
        unsigned long long key = sk[r];
        unsigned idx = 0xFFFFFFFFu - (unsigned)(key & 0xFFFFFFFFull);
        float sc = __uint_as_float((unsigned)(key >> 32));
        float4 o = make_float4(0.f, 0.f, 0.f, 0.f);
        if (idx < (unsigned)n) {
            float4 a = anch4[idx];   // [y1, x1, y2, x2]
            float4 e = enc4[idx];    // [ty, tx, th, tw]
            float ha = a.z - a.x, wa = a.w - a.y;
            float cya = a.x + 0.5f * ha, cxa = a.y + 0.5f * wa;
            float cy = e.x * ha + cya;
            float cx = e.y * wa + cxa;
            float h  = expf(e.z) * ha;
            float w  = expf(e.w) * wa;
            o = make_float4(cy - 0.5f * h, cx - 0.5f * w, cy + 0.5f * h, cx + 0.5f * w);
        } else {
            sc = 0.f;
        }
        ((float4*)g_boxes)[r] = o;
        g_scores[r] = sc;
    }
}

// ---------------- K6: IoU bitmask, torchvision-style ------------------------
// block (bx=col group, by=row group), only upper triangle bx>=by is ever read.
__global__ void mask_k() {
    int bx = blockIdx.x, by = blockIdx.y;
    if (bx < by) return;
    __shared__ float4 colb[64];
    int t = threadIdx.x;
    colb[t] = ((const float4*)g_boxes)[bx * 64 + t];
    __syncthreads();
    int i = by * 64 + t;
    float4 rb = ((const float4*)g_boxes)[i];
    float areaA = (rb.z - rb.x) * (rb.w - rb.y);
    unsigned long long m = 0ull;
    int jbase = bx * 64;
#pragma unroll 4
    for (int c = 0; c < 64; c++) {
        int j = jbase + c;
        if (j > i) {
            float4 cb = colb[c];
            float iy1 = fmaxf(rb.x, cb.x), ix1 = fmaxf(rb.y, cb.y);
            float iy2 = fminf(rb.z, cb.z), ix2 = fminf(rb.w, cb.w);
            float inter = fmaxf(iy2 - iy1, 0.f) * fmaxf(ix2 - ix1, 0.f);
            float areaB = (cb.z - cb.x) * (cb.w - cb.y);
            float uni = areaA + areaB - inter;
            float iou = inter / fmaxf(uni, 1e-8f);
            if (iou > IOU_THRF) m |= (1ull << c);
        }
    }
    g_mask[(size_t)i * NB + bx] = m;
}

// ---------------- K7: group-restructured sequential greedy reduce + output --
__global__ void nms_k(float* __restrict__ out) {
    __shared__ unsigned long long s_col[64];
    __shared__ unsigned long long s_cross;
    __shared__ int s_kept[NPOST];
    __shared__ int s_kc;
    int t = threadIdx.x;
    int kcount = 0;

    for (int g = 0; g < NB; ++g) {
        int base = g * 64;
        int n = NPRE - base; if (n > 64) n = 64;
        if (t == 0) s_cross = 0ull;
        if (t < n) s_col[t] = g_mask[(size_t)(base + t) * NB + g];
        __syncthreads();
        // cross-group suppression: OR column g of every kept earlier row (parallel)
        unsigned long long p = 0ull;
        for (int q = t; q < kcount; q += blockDim.x)
            p |= g_mask[(size_t)s_kept[q] * NB + g];
        if (p) atomicOr(&s_cross, p);
        __syncthreads();
        // in-group greedy resolution: strictly sequential but register/shared only
        if (t == 0) {
            unsigned long long word = s_cross;
            int kc = kcount;
            for (int k = 0; k < n; k++) {
                if (!((word >> k) & 1ull)) {
                    s_kept[kc] = base + k;
                    word |= s_col[k];
                    if (++kc == NPOST) break;
                }
            }
            s_kc = kc;
        }
        __syncthreads();
        kcount = s_kc;
        if (kcount >= NPOST) break;
    }

    // write output: [2000 x 4] boxes, then [2000] scores, zero-padded
    for (int o = t; o < NPOST; o += blockDim.x) {
        if (o < kcount) {
            int i = s_kept[o];
            ((float4*)out)[o] = ((const float4*)g_boxes)[i];
            out[NPOST * 4 + o] = g_scores[i];
        } else {
            ((float4*)out)[o] = make_float4(0.f, 0.f, 0.f, 0.f);
            out[NPOST * 4 + o] = 0.f;
        }
    }
}

// ---------------- launch ----------------------------------------------------
extern "C" void kernel_launch(void* const* d_in, const int* in_sizes, int n_in,
                              void* d_out, int out_size) {
    const float* enc    = (const float*)d_in[0];  // encoded_bboxes [N,4]
    const float* anch   = (const float*)d_in[1];  // anchors        [N,4]
    const float* scores = (const float*)d_in[2];  // scores         [N]
    float* out = (float*)d_out;                   // 2000*4 boxes + 2000 scores
    int n = in_sizes[2];

    // >48KB dynamic smem for the sort kernel (host attr call; legal in capture)
    cudaFuncSetAttribute(sort_decode_k, cudaFuncAttributeMaxDynamicSharedMemorySize,
                         CAND_MAX * (int)sizeof(unsigned long long));

    zero_k<<<(HB + 255) / 256, 256>>>();
    {
        int blocks = (n + 255) / 256; if (blocks > 4096) blocks = 4096;
        hist_k<<<blocks, 256>>>(scores, n);
        thresh_k<<<1, 1024>>>();
        compact_k<<<blocks, 256>>>(scores, n);
    }
    sort_decode_k<<<1, 1024, CAND_MAX * sizeof(unsigned long long)>>>(enc, anch, n);
    mask_k<<<dim3(NB, NB), 64>>>();
    nms_k<<<1, 256>>>(out);
}

// round 2
// speedup vs baseline: 1.0745x; 1.0745x over previous
#include <cuda_runtime.h>
#include <stdint.h>

// Problem constants (fixed by the reference).
#define NPRE     6000
#define NPOST    2000
#define NB       94          // ceil(NPRE/64)
#define NROWS    (NB * 64)   // 6016, padded
#define HB       32768       // score histogram buckets (scores in [0,1))
#define CAND_MAX 8192        // candidate capacity for the top-k sort
#define GRP_CHUNK 12         // mask/nms groups per chunk
#define NCHUNK    8          // 8*12 = 96 >= 94

// ---------------- persistent device scratch (no allocations allowed) --------
__device__ unsigned           g_hist[HB];
__device__ int                g_ncand;
__device__ int                g_thresh;
__device__ unsigned long long g_cand[CAND_MAX];
// SoA boxes (padded rows >= NPRE are zero)
__device__ float              g_y1[NROWS], g_x1[NROWS], g_y2[NROWS], g_x2[NROWS];
__device__ float              g_pa[NROWS];      // 0.7f * area
__device__ float              g_scores[NROWS];
__device__ unsigned long long g_mask[(size_t)NROWS * NB];
__device__ int                g_kept[NPOST];
__device__ int                g_kcount;
__device__ int                g_done;

// ---------------- K1: zero histogram + state --------------------------------
__global__ void zero_k() {
    int i = blockIdx.x * blockDim.x + threadIdx.x;
    if (i < HB) g_hist[i] = 0u;
    if (i == 0) { g_ncand = 0; g_kcount = 0; g_done = 0; }
}

__device__ __forceinline__ int score_bucket(float s) {
    int b = (int)(s * 32768.0f);
    return max(0, min(HB - 1, b));
}

// ---------------- K2: histogram of scores (float4 vectorized) ---------------
__global__ void hist_k(const float4* __restrict__ s4, int n4) {
    int i = blockIdx.x * blockDim.x + threadIdx.x;
    int stride = gridDim.x * blockDim.x;
    for (; i < n4; i += stride) {
        float4 v = s4[i];
        atomicAdd(&g_hist[score_bucket(v.x)], 1u);
        atomicAdd(&g_hist[score_bucket(v.y)], 1u);
        atomicAdd(&g_hist[score_bucket(v.z)], 1u);
        atomicAdd(&g_hist[score_bucket(v.w)], 1u);
    }
}

// ---------------- K3: find threshold bucket (descending suffix scan) --------
__global__ void thresh_k() {
    __shared__ unsigned s[1024];
    int t = threadIdx.x;
    int lo = HB - (t + 1) * 32;  // thread owns buckets [lo, lo+32), t=0 = top
    unsigned sum = 0;
#pragma unroll
    for (int b = 0; b < 32; b++) sum += g_hist[lo + b];
    s[t] = sum;
    __syncthreads();
    for (int off = 1; off < 1024; off <<= 1) {
        unsigned v = (t >= off) ? s[t - off] : 0u;
        __syncthreads();
        s[t] += v;
        __syncthreads();
    }
    unsigned incl = s[t];
    unsigned excl = incl - sum;
    if (excl < (unsigned)NPRE && incl >= (unsigned)NPRE) {
        unsigned cum = excl;
        for (int b = lo + 31; b >= lo; --b) {
            cum += g_hist[b];
            if (cum >= (unsigned)NPRE) { g_thresh = b; break; }
        }
    }
    if (t == 1023 && s[1023] < (unsigned)NPRE) g_thresh = 0;  // take all
}

// ---------------- K4: compact candidate keys (float4 vectorized) ------------
__global__ void compact_k(const float4* __restrict__ s4, int n4) {
    int T = g_thresh;
    int i = blockIdx.x * blockDim.x + threadIdx.x;
    int stride = gridDim.x * blockDim.x;
    for (; i < n4; i += stride) {
        float4 v = s4[i];
        float e[4] = {v.x, v.y, v.z, v.w};
#pragma unroll
        for (int c = 0; c < 4; c++) {
            if (score_bucket(e[c]) >= T) {
                int p = atomicAdd(&g_ncand, 1);
                if (p < CAND_MAX) {
                    unsigned idx = (unsigned)(4 * i + c);
                    g_cand[p] = ((unsigned long long)__float_as_uint(e[c]) << 32)
                              | (unsigned long long)(0xFFFFFFFFu - idx);
                }
            }
        }
    }
}

// ---------------- K5: bitonic sort (descending) + gather + decode -----------
__global__ void sort_decode_k(const float* __restrict__ enc,
                              const float* __restrict__ anch, int n) {
    extern __shared__ unsigned long long sk[];
    int t = threadIdx.x;                               // 1024 threads
    int nc = g_ncand; if (nc > CAND_MAX) nc = CAND_MAX;
    for (int i = t; i < CAND_MAX; i += 1024) sk[i] = (i < nc) ? g_cand[i] : 0ull;
    __syncthreads();

    for (int k = 2; k <= CAND_MAX; k <<= 1) {
        // shared passes: j >= 8
        for (int j = k >> 1; j >= 8; j >>= 1) {
            for (int p = t; p < CAND_MAX / 2; p += 1024) {
                int i = ((p & ~(j - 1)) << 1) | (p & (j - 1));
                int x = i | j;
                unsigned long long a = sk[i], b = sk[x];
                bool desc = ((i & k) == 0);
                if (desc ? (a < b) : (a > b)) { sk[i] = b; sk[x] = a; }
            }
            __syncthreads();
        }
        // register phase: j in {min(k/2,4), ..., 1} on contiguous 8-chunks
        {
            unsigned long long r[8];
            int b0 = t * 8;
#pragma unroll
            for (int e = 0; e < 8; e++) r[e] = sk[b0 + e];
            int jj = (k >> 1) < 4 ? (k >> 1) : 4;
            for (int j = jj; j >= 1; j >>= 1) {
#pragma unroll
                for (int e = 0; e < 8; e++) {
                    if (!(e & j)) {
                        int i = b0 + e;
                        bool desc = ((i & k) == 0);
                        unsigned long long a = r[e], b = r[e | j];
                        if (desc ? (a < b) : (a > b)) { r[e] = b; r[e | j] = a; }
                    }
                }
            }
#pragma unroll
            for (int e = 0; e < 8; e++) sk[b0 + e] = r[e];
            __syncthreads();
        }
    }

    // decode top NPRE boxes into SoA; pad rows to NROWS with zeros
    const float4* enc4  = (const float4*)enc;
    const float4* anch4 = (const float4*)anch;
    for (int r = t; r < NROWS; r += 1024) {
        float y1 = 0.f, x1 = 0.f, y2 = 0.f, x2 = 0.f, sc = 0.f;
        if (r < NPRE) {
            unsigned long long key = sk[r];
            unsigned idx = 0xFFFFFFFFu - (unsigned)(key & 0xFFFFFFFFull);
            if (idx < (unsigned)n) {
                sc = __uint_as_float((unsigned)(key >> 32));
                float4 a = anch4[idx];   // [y1, x1, y2, x2]
                float4 e = enc4[idx];    // [ty, tx, th, tw]
                float ha = a.z - a.x, wa = a.w - a.y;
                float cya = a.x + 0.5f * ha, cxa = a.y + 0.5f * wa;
                float cy = e.x * ha + cya;
                float cx = e.y * wa + cxa;
                float h  = expf(e.z) * ha;
                float w  = expf(e.w) * wa;
                y1 = cy - 0.5f * h; x1 = cx - 0.5f * w;
                y2 = cy + 0.5f * h; x2 = cx + 0.5f * w;
            }
        }
        g_y1[r] = y1; g_x1[r] = x1; g_y2[r] = y2; g_x2[r] = x2;
        g_pa[r] = 0.7f * (y2 - y1) * (x2 - x1);
        g_scores[r] = sc;
    }
}

// ---------------- K6: IoU bitmask for a chunk of columns --------------------
// iou > 0.7  <=>  1.7*inter > 0.7*areaA + 0.7*areaB   (union clamp irrelevant
// for non-degenerate boxes; degenerate zero-pad boxes give inter=0 -> false)
__global__ void mask_k(int col0) {
    if (*(volatile int*)&g_done) return;
    int bx = col0 + blockIdx.x;
    int by = blockIdx.y;
    if (bx >= NB || by > bx) return;

    __shared__ float4 colb[64];
    __shared__ float  colp[64];
    int t = threadIdx.x;
    int j = bx * 64 + t;
    colb[t] = make_float4(g_y1[j], g_x1[j], g_y2[j], g_x2[j]);
    colp[t] = g_pa[j];
    __syncthreads();

    int i = by * 64 + t;
    float y1 = g_y1[i], x1 = g_x1[i], y2 = g_y2[i], x2 = g_x2[i];
    float pa = g_pa[i];
    unsigned long long m = 0ull;

    if (bx > by) {
#pragma unroll 16
        for (int c = 0; c < 64; c++) {
            float4 cb = colb[c];
            float iy1 = fmaxf(y1, cb.x), ix1 = fmaxf(x1, cb.y);
            float iy2 = fminf(y2, cb.z), ix2 = fminf(x2, cb.w);
            float dy = fmaxf(iy2 - iy1, 0.f), dx = fmaxf(ix2 - ix1, 0.f);
            float inter = dy * dx;
            bool cond = fmaf(1.7f, inter, -pa) > colp[c];
            m |= ((unsigned long long)cond) << c;
        }
    } else {  // diagonal block: only c > t
        for (int c = t + 1; c < 64; c++) {
            float4 cb = colb[c];
            float iy1 = fmaxf(y1, cb.x), ix1 = fmaxf(x1, cb.y);
            float iy2 = fminf(y2, cb.z), ix2 = fminf(x2, cb.w);
            float dy = fmaxf(iy2 - iy1, 0.f), dx = fmaxf(ix2 - ix1, 0.f);
            float inter = dy * dx;
            bool cond = fmaf(1.7f, inter, -pa) > colp[c];
            m |= ((unsigned long long)cond) << c;
        }
    }
    g_mask[(size_t)i * NB + bx] = m;
}

// ---------------- K7: NMS partial reduce over a chunk of groups -------------
__global__ void nms_part_k(int g0) {
    if (*(volatile int*)&g_done) return;
    __shared__ int s_kept[NPOST];
    __shared__ unsigned long long s_col[64];
    __shared__ unsigned long long s_cross;
    __shared__ int s_kc;
    int t = threadIdx.x;                       // 256 threads
    int kc0 = g_kcount;
    for (int i = t; i < kc0; i += 256) s_kept[i] = g_kept[i];
    __syncthreads();

    int kcount = kc0;
    int g1 = min(g0 + GRP_CHUNK, NB);
    for (int g = g0; g < g1; ++g) {
        int base = g * 64;
        int nrows = NPRE - base; if (nrows > 64) nrows = 64;
        if (t == 0) s_cross = 0ull;
        if (t < 64) s_col[t] = g_mask[(size_t)(base + t) * NB + g];
        __syncthreads();
        // cross-group suppression: OR column g of every kept earlier row
        unsigned long long p = 0ull;
        for (int q = t; q < kcount; q += 256)
            p |= g_mask[(size_t)s_kept[q] * NB + g];
        if (p) atomicOr(&s_cross, p);
        __syncthreads();
        // in-group greedy resolution: 2-way speculative serial chain
        if (t == 0) {
            unsigned long long avail = ~s_cross;
            if (nrows < 64) avail &= (1ull << nrows) - 1ull;
            int kc = kcount;
            while (avail && kc < NPOST) {
                int k1 = __ffsll((long long)avail) - 1;
                unsigned long long r1 = avail & (avail - 1);
                unsigned long long c1 = s_col[k1];
                if (r1 == 0ull) { s_kept[kc++] = base + k1; break; }
                int k2 = __ffsll((long long)r1) - 1;
                unsigned long long c2 = s_col[k2];   // speculative parallel load
                s_kept[kc++] = base + k1;
                unsigned long long r2 = r1 & (r1 - 1);
                if (!((c1 >> k2) & 1ull)) {
                    if (kc < NPOST) { s_kept[kc++] = base + k2; avail = r2 & ~c1 & ~c2; }
                    else avail = 0ull;
                } else {
                    avail = r2 & ~c1;
                }
            }
            s_kc = kc;
        }
        __syncthreads();
        kcount = s_kc;
        if (kcount >= NPOST) break;
    }

    for (int i = kc0 + t; i < kcount; i += 256) g_kept[i] = s_kept[i];
    if (t == 0) {
        g_kcount = kcount;
        if (kcount >= NPOST || g1 >= NB) g_done = 1;
    }
    __threadfence();
}

// ---------------- K8: write output ------------------------------------------
__global__ void out_k(float* __restrict__ out) {
    int kcount = g_kcount;
    int o = blockIdx.x * blockDim.x + threadIdx.x;
    if (o < NPOST) {
        if (o < kcount) {
            int i = g_kept[o];
            ((float4*)out)[o] = make_float4(g_y1[i], g_x1[i], g_y2[i], g_x2[i]);
            out[NPOST * 4 + o] = g_scores[i];
        } else {
            ((float4*)out)[o] = make_float4(0.f, 0.f, 0.f, 0.f);
            out[NPOST * 4 + o] = 0.f;
        }
    }
}

// ---------------- launch ----------------------------------------------------
extern "C" void kernel_launch(void* const* d_in, const int* in_sizes, int n_in,
                              void* d_out, int out_size) {
    const float* enc    = (const float*)d_in[0];  // encoded_bboxes [N,4]
    const float* anch   = (const float*)d_in[1];  // anchors        [N,4]
    const float* scores = (const float*)d_in[2];  // scores         [N]
    float* out = (float*)d_out;                   // 2000*4 boxes + 2000 scores
    int n = in_sizes[2];
    int n4 = n / 4;                               // N = 2,000,000 divisible by 4

    cudaFuncSetAttribute(sort_decode_k, cudaFuncAttributeMaxDynamicSharedMemorySize,
                         CAND_MAX * (int)sizeof(unsigned long long));

    zero_k<<<(HB + 255) / 256, 256>>>();
    {
        int blocks = (n4 + 255) / 256; if (blocks > 2048) blocks = 2048;
        hist_k<<<blocks, 256>>>((const float4*)scores, n4);
        thresh_k<<<1, 1024>>>();
        compact_k<<<blocks, 256>>>((const float4*)scores, n4);
    }
    sort_decode_k<<<1, 1024, CAND_MAX * sizeof(unsigned long long)>>>(enc, anch, n);

    for (int c = 0; c < NCHUNK; c++) {
        int c0 = c * GRP_CHUNK;
        int ymax = c0 + GRP_CHUNK; if (ymax > NB) ymax = NB;
        mask_k<<<dim3(GRP_CHUNK, ymax), 64>>>(c0);
        nms_part_k<<<1, 256>>>(c0);
    }
    out_k<<<(NPOST + 255) / 256, 256>>>(out);
}

// round 3
// speedup vs baseline: 1.4984x; 1.3946x over previous
#include <cuda_runtime.h>
#include <stdint.h>

// Problem constants (fixed by the reference).
#define NPRE     6000
#define NPOST    2000
#define NB       94          // ceil(NPRE/64)
#define NROWS    (NB * 64)   // 6016, padded
#define HB       32768       // score histogram buckets (scores in [0,1))
#define CAND_MAX 8192
#define BCAP     256         // per-bucket sort capacity

// ---------------- persistent device scratch ---------------------------------
__device__ unsigned           g_hist[HB];
__device__ unsigned           g_cnt[HB];
__device__ unsigned           g_base[HB];   // descending exclusive rank base
__device__ int                g_thresh;
__device__ unsigned long long g_cand[CAND_MAX];
// SoA boxes (padded rows >= NPRE are zero)
__device__ float              g_y1[NROWS], g_x1[NROWS], g_y2[NROWS], g_x2[NROWS];
__device__ float              g_pa[NROWS];      // 0.7f * area
__device__ float              g_scores[NROWS];
__device__ unsigned long long g_mask[(size_t)NROWS * NB];
__device__ int                g_kept[NPOST];
__device__ int                g_kcount;
__device__ int                g_done;

__device__ __forceinline__ int score_bucket(float s) {
    int b = (int)(s * 32768.0f);
    return max(0, min(HB - 1, b));
}

// ---------------- K1: zero histograms + state -------------------------------
__global__ void zero_k() {
    int i = blockIdx.x * blockDim.x + threadIdx.x;
    if (i < HB) { g_hist[i] = 0u; g_cnt[i] = 0u; }
    if (i == 0) { g_kcount = 0; g_done = 0; }
}

// ---------------- K2: histogram of scores (float4) --------------------------
__global__ void hist_k(const float4* __restrict__ s4, int n4) {
    int i = blockIdx.x * blockDim.x + threadIdx.x;
    int stride = gridDim.x * blockDim.x;
    for (; i < n4; i += stride) {
        float4 v = s4[i];
        atomicAdd(&g_hist[score_bucket(v.x)], 1u);
        atomicAdd(&g_hist[score_bucket(v.y)], 1u);
        atomicAdd(&g_hist[score_bucket(v.z)], 1u);
        atomicAdd(&g_hist[score_bucket(v.w)], 1u);
    }
}

// ---------------- K3: threshold + per-bucket rank bases ---------------------
__global__ void thresh_k() {
    __shared__ unsigned s[1024];
    int t = threadIdx.x;
    int lo = HB - (t + 1) * 32;  // thread owns buckets [lo, lo+32); t=0 = top
    unsigned cnts[32];
    unsigned sum = 0;
#pragma unroll
    for (int b = 0; b < 32; b++) { cnts[b] = g_hist[lo + b]; sum += cnts[b]; }
    s[t] = sum;
    __syncthreads();
    for (int off = 1; off < 1024; off <<= 1) {
        unsigned v = (t >= off) ? s[t - off] : 0u;
        __syncthreads();
        s[t] += v;
        __syncthreads();
    }
    unsigned run = s[t] - sum;   // count strictly above this chunk
    for (int b = 31; b >= 0; --b) {
        g_base[lo + b] = run;
        unsigned c = cnts[b];
        if (run < (unsigned)NPRE && run + c >= (unsigned)NPRE) g_thresh = lo + b;
        run += c;
    }
    if (t == 1023 && s[1023] < (unsigned)NPRE) g_thresh = 0;  // degenerate
}

// ---------------- K4: counting-sort scatter of candidates -------------------
__global__ void compact_k(const float4* __restrict__ s4, int n4) {
    int T = g_thresh;
    int i = blockIdx.x * blockDim.x + threadIdx.x;
    int stride = gridDim.x * blockDim.x;
    for (; i < n4; i += stride) {
        float4 v = s4[i];
        float e[4] = {v.x, v.y, v.z, v.w};
#pragma unroll
        for (int c = 0; c < 4; c++) {
            int b = score_bucket(e[c]);
            if (b >= T) {
                unsigned pos = g_base[b] + atomicAdd(&g_cnt[b], 1u);
                if (pos < CAND_MAX) {
                    unsigned idx = (unsigned)(4 * i + c);
                    g_cand[pos] = ((unsigned long long)__float_as_uint(e[c]) << 32)
                                | (unsigned long long)(0xFFFFFFFFu - idx);
                }
            }
        }
    }
}

// ---------------- K5: per-bucket micro bitonic sorts (descending) -----------
__global__ void bsort_k() {
    __shared__ unsigned long long s[BCAP];
    int T = g_thresh;
    int t = threadIdx.x;                           // 128 threads
    for (int b = T + blockIdx.x; b < HB; b += gridDim.x) {
        unsigned base = g_base[b];
        if (base >= (unsigned)NPRE) continue;      // never read
        unsigned cnt = g_cnt[b];
        if (cnt <= 1) continue;
        int m = (cnt < (unsigned)BCAP) ? (int)cnt : BCAP;
#pragma unroll
        for (int e = 0; e < 2; e++) {
            int i = t + e * 128;
            s[i] = (i < m) ? g_cand[base + i] : 0ull;
        }
        __syncthreads();
        for (int k = 2; k <= BCAP; k <<= 1) {
            for (int j = k >> 1; j > 0; j >>= 1) {
                int i = ((t & ~(j - 1)) << 1) | (t & (j - 1));
                int x = i | j;
                unsigned long long a = s[i], bb = s[x];
                bool desc = ((i & k) == 0);
                if (desc ? (a < bb) : (a > bb)) { s[i] = bb; s[x] = a; }
                __syncthreads();
            }
        }
#pragma unroll
        for (int e = 0; e < 2; e++) {
            int i = t + e * 128;
            if (i < m) g_cand[base + i] = s[i];
        }
        __syncthreads();
    }
}

// ---------------- K6: decode top NPRE boxes into SoA ------------------------
__global__ void decode_k(const float* __restrict__ enc,
                         const float* __restrict__ anch, int n) {
    int r = blockIdx.x * blockDim.x + threadIdx.x;
    if (r >= NROWS) return;
    float y1 = 0.f, x1 = 0.f, y2 = 0.f, x2 = 0.f, sc = 0.f;
    if (r < NPRE) {
        unsigned long long key = g_cand[r];
        unsigned idx = 0xFFFFFFFFu - (unsigned)(key & 0xFFFFFFFFull);
        if (idx < (unsigned)n) {
            sc = __uint_as_float((unsigned)(key >> 32));
            float4 a = ((const float4*)anch)[idx];   // [y1, x1, y2, x2]
            float4 e = ((const float4*)enc)[idx];    // [ty, tx, th, tw]
            float ha = a.z - a.x, wa = a.w - a.y;
            float cya = a.x + 0.5f * ha, cxa = a.y + 0.5f * wa;
            float cy = e.x * ha + cya;
            float cx = e.y * wa + cxa;
            float h  = expf(e.z) * ha;
            float w  = expf(e.w) * wa;
            y1 = cy - 0.5f * h; x1 = cx - 0.5f * w;
            y2 = cy + 0.5f * h; x2 = cx + 0.5f * w;
        }
    }
    g_y1[r] = y1; g_x1[r] = x1; g_y2[r] = y2; g_x2[r] = x2;
    g_pa[r] = 0.7f * (y2 - y1) * (x2 - x1);
    g_scores[r] = sc;
}

// ---------------- K7: IoU bitmask (division-free) ---------------------------
// iou > 0.7  <=>  1.7*inter > 0.7*areaA + 0.7*areaB
__global__ void mask_k(int col0) {
    if (*(volatile int*)&g_done) return;
    int bx = col0 + blockIdx.x;
    int by = blockIdx.y;
    if (bx >= NB || by > bx) return;

    __shared__ float4 colb[64];
    __shared__ float  colp[64];
    int t = threadIdx.x;
    int j = bx * 64 + t;
    colb[t] = make_float4(g_y1[j], g_x1[j], g_y2[j], g_x2[j]);
    colp[t] = g_pa[j];
    __syncthreads();

    int i = by * 64 + t;
    float y1 = g_y1[i], x1 = g_x1[i], y2 = g_y2[i], x2 = g_x2[i];
    float pa = g_pa[i];
    unsigned long long m = 0ull;

    if (bx > by) {
#pragma unroll 16
        for (int c = 0; c < 64; c++) {
            float4 cb = colb[c];
            float iy1 = fmaxf(y1, cb.x), ix1 = fmaxf(x1, cb.y);
            float iy2 = fminf(y2, cb.z), ix2 = fminf(x2, cb.w);
            float dy = fmaxf(iy2 - iy1, 0.f), dx = fmaxf(ix2 - ix1, 0.f);
            bool cond = fmaf(1.7f, dy * dx, -pa) > colp[c];
            m |= ((unsigned long long)cond) << c;
        }
    } else {  // diagonal block: only c > t
        for (int c = t + 1; c < 64; c++) {
            float4 cb = colb[c];
            float iy1 = fmaxf(y1, cb.x), ix1 = fmaxf(x1, cb.y);
            float iy2 = fminf(y2, cb.z), ix2 = fminf(x2, cb.w);
            float dy = fmaxf(iy2 - iy1, 0.f), dx = fmaxf(ix2 - ix1, 0.f);
            bool cond = fmaf(1.7f, dy * dx, -pa) > colp[c];
            m |= ((unsigned long long)cond) << c;
        }
    }
    g_mask[(size_t)i * NB + bx] = m;
}

// ---------------- K8: NMS partial reduce over group range -------------------
__global__ void nms_part_k(int g0, int g1) {
    if (*(volatile int*)&g_done) return;
    __shared__ int s_kept[NPOST];
    __shared__ unsigned long long s_col[64];
    __shared__ unsigned long long s_cross;
    __shared__ int s_kc;
    int t = threadIdx.x;                       // 256 threads
    int kc0 = g_kcount;
    for (int i = t; i < kc0; i += 256) s_kept[i] = g_kept[i];
    __syncthreads();

    int kcount = kc0;
    if (g1 > NB) g1 = NB;
    for (int g = g0; g < g1; ++g) {
        int base = g * 64;
        int nrows = NPRE - base; if (nrows > 64) nrows = 64;
        if (t == 0) s_cross = 0ull;
        if (t < 64) s_col[t] = g_mask[(size_t)(base + t) * NB + g];
        __syncthreads();
        // cross-group suppression: OR column g of every kept earlier row
        unsigned long long p = 0ull;
        for (int q = t; q < kcount; q += 256)
            p |= g_mask[(size_t)s_kept[q] * NB + g];
        if (p) atomicOr(&s_cross, p);
        __syncthreads();
        // in-group greedy resolution: 2-way speculative serial chain
        if (t == 0) {
            unsigned long long avail = ~s_cross;
            if (nrows < 64) avail &= (1ull << nrows) - 1ull;
            int kc = kcount;
            while (avail && kc < NPOST) {
                int k1 = __ffsll((long long)avail) - 1;
                unsigned long long r1 = avail & (avail - 1);
                unsigned long long c1 = s_col[k1];
                if (r1 == 0ull) { s_kept[kc++] = base + k1; break; }
                int k2 = __ffsll((long long)r1) - 1;
                unsigned long long c2 = s_col[k2];   // speculative parallel load
                s_kept[kc++] = base + k1;
                unsigned long long r2 = r1 & (r1 - 1);
                if (!((c1 >> k2) & 1ull)) {
                    if (kc < NPOST) { s_kept[kc++] = base + k2; avail = r2 & ~c1 & ~c2; }
                    else avail = 0ull;
                } else {
                    avail = r2 & ~c1;
                }
            }
            s_kc = kc;
        }
        __syncthreads();
        kcount = s_kc;
        if (kcount >= NPOST) break;
    }

    for (int i = kc0 + t; i < kcount; i += 256) g_kept[i] = s_kept[i];
    if (t == 0) {
        g_kcount = kcount;
        if (kcount >= NPOST || g1 >= NB) g_done = 1;
    }
    __threadfence();
}

// ---------------- K9: write output ------------------------------------------
__global__ void out_k(float* __restrict__ out) {
    int kcount = g_kcount;
    int o = blockIdx.x * blockDim.x + threadIdx.x;
    if (o < NPOST) {
        if (o < kcount) {
            int i = g_kept[o];
            ((float4*)out)[o] = make_float4(g_y1[i], g_x1[i], g_y2[i], g_x2[i]);
            out[NPOST * 4 + o] = g_scores[i];
        } else {
            ((float4*)out)[o] = make_float4(0.f, 0.f, 0.f, 0.f);
            out[NPOST * 4 + o] = 0.f;
        }
    }
}

// ---------------- launch ----------------------------------------------------
extern "C" void kernel_launch(void* const* d_in, const int* in_sizes, int n_in,
                              void* d_out, int out_size) {
    const float* enc    = (const float*)d_in[0];  // encoded_bboxes [N,4]
    const float* anch   = (const float*)d_in[1];  // anchors        [N,4]
    const float* scores = (const float*)d_in[2];  // scores         [N]
    float* out = (float*)d_out;                   // 2000*4 boxes + 2000 scores
    int n = in_sizes[2];
    int n4 = n / 4;                               // divisible by 4 here

    zero_k<<<(HB + 255) / 256, 256>>>();
    hist_k<<<512, 256>>>((const float4*)scores, n4);
    thresh_k<<<1, 1024>>>();
    compact_k<<<512, 256>>>((const float4*)scores, n4);
    bsort_k<<<256, 128>>>();
    decode_k<<<(NROWS + 127) / 128, 128>>>(enc, anch, n);

    // chunked mask+NMS with early-exit flag; typical exit in first chunk
    mask_k<<<dim3(48, 48), 64>>>(0);
    nms_part_k<<<1, 256>>>(0, 48);
    mask_k<<<dim3(24, 72), 64>>>(48);
    nms_part_k<<<1, 256>>>(48, 72);
    mask_k<<<dim3(22, 94), 64>>>(72);
    nms_part_k<<<1, 256>>>(72, 94);

    out_k<<<(NPOST + 255) / 256, 256>>>(out);
}

// round 4
// speedup vs baseline: 1.8317x; 1.2224x over previous
#include <cuda_runtime.h>
#include <stdint.h>

// Problem constants (fixed by the reference).
#define NPRE     6000
#define NPOST    2000
#define NB       94          // ceil(NPRE/64)
#define NROWS    (NB * 64)   // 6016, padded
#define HB       32768       // score histogram buckets (scores in [0,1))
#define CAND_MAX 8192
#define BCAP     256         // per-bucket sort capacity
#define SCUT     (HB - 256)  // stash cut bucket
#define STASH_CAP 32768

// ---------------- persistent device scratch ---------------------------------
__device__ unsigned           g_hist[HB];
__device__ unsigned           g_cnt[HB];
__device__ unsigned           g_base[HB];   // descending exclusive rank base
__device__ int                g_thresh;
__device__ int                g_nstash;
__device__ unsigned long long g_stash[STASH_CAP];
__device__ unsigned long long g_cand[CAND_MAX];
// SoA boxes (padded rows >= NPRE are zero)
__device__ float              g_y1[NROWS], g_x1[NROWS], g_y2[NROWS], g_x2[NROWS];
__device__ float              g_pa[NROWS];      // 0.7f * area
__device__ float              g_scores[NROWS];
// transposed mask: g_maskT[col_group][row]
__device__ unsigned long long g_maskT[NB][NROWS];
__device__ unsigned long long g_alive[NB];
__device__ int                g_kept[NPOST];
__device__ int                g_kcount;
__device__ int                g_done;

__device__ __forceinline__ int score_bucket(float s) {
    int b = (int)(s * 32768.0f);
    return max(0, min(HB - 1, b));
}

// ---------------- K1: zero histograms + state -------------------------------
__global__ void zero_k() {
    int i = blockIdx.x * blockDim.x + threadIdx.x;
    if (i < HB) { g_hist[i] = 0u; g_cnt[i] = 0u; }
    if (i < NB) g_alive[i] = 0ull;
    if (i == 0) { g_kcount = 0; g_done = 0; g_nstash = 0; }
}

// ---------------- K2: histogram + stash of top-bucket candidates ------------
__global__ void hist_stash_k(const float4* __restrict__ s4, int n4) {
    int i = blockIdx.x * blockDim.x + threadIdx.x;
    int stride = gridDim.x * blockDim.x;
    for (; i < n4; i += stride) {
        float4 v = s4[i];
        float e[4] = {v.x, v.y, v.z, v.w};
#pragma unroll
        for (int c = 0; c < 4; c++) {
            int b = score_bucket(e[c]);
            atomicAdd(&g_hist[b], 1u);
            if (b >= SCUT) {
                int p = atomicAdd(&g_nstash, 1);
                if (p < STASH_CAP) {
                    unsigned idx = (unsigned)(4 * i + c);
                    g_stash[p] = ((unsigned long long)__float_as_uint(e[c]) << 32)
                               | (unsigned long long)(0xFFFFFFFFu - idx);
                }
            }
        }
    }
}

// ---------------- K3: threshold + per-bucket rank bases ---------------------
__global__ void thresh_k() {
    __shared__ unsigned s[1024];
    int t = threadIdx.x;
    int lo = HB - (t + 1) * 32;  // thread owns buckets [lo, lo+32); t=0 = top
    unsigned cnts[32];
    const uint4* h4 = (const uint4*)g_hist;
#pragma unroll
    for (int k = 0; k < 8; k++) {
        uint4 u = h4[(lo >> 2) + k];
        cnts[4 * k + 0] = u.x; cnts[4 * k + 1] = u.y;
        cnts[4 * k + 2] = u.z; cnts[4 * k + 3] = u.w;
    }
    unsigned sum = 0;
#pragma unroll
    for (int b = 0; b < 32; b++) sum += cnts[b];
    s[t] = sum;
    __syncthreads();
    for (int off = 1; off < 1024; off <<= 1) {
        unsigned v = (t >= off) ? s[t - off] : 0u;
        __syncthreads();
        s[t] += v;
        __syncthreads();
    }
    unsigned run = s[t] - sum;   // count strictly above this chunk
    for (int b = 31; b >= 0; --b) {
        g_base[lo + b] = run;
        unsigned c = cnts[b];
        if (run < (unsigned)NPRE && run + c >= (unsigned)NPRE) g_thresh = lo + b;
        run += c;
    }
    if (t == 1023 && s[1023] < (unsigned)NPRE) g_thresh = 0;  // degenerate
}

// ---------------- K4: counting-sort scatter (stash fast path / full fallback)
__global__ void compact_k(const float4* __restrict__ s4, int n4) {
    int T = g_thresh;
    bool valid = (T >= SCUT) && (g_nstash <= STASH_CAP);
    int tid = blockIdx.x * blockDim.x + threadIdx.x;
    int stride = gridDim.x * blockDim.x;
    if (valid) {
        int ns = g_nstash;
        for (int i = tid; i < ns; i += stride) {
            unsigned long long key = g_stash[i];
            int b = score_bucket(__uint_as_float((unsigned)(key >> 32)));
            if (b >= T) {
                unsigned pos = g_base[b] + atomicAdd(&g_cnt[b], 1u);
                if (pos < CAND_MAX) g_cand[pos] = key;
            }
        }
    } else {
        for (int i = tid; i < n4; i += stride) {
            float4 v = s4[i];
            float e[4] = {v.x, v.y, v.z, v.w};
#pragma unroll
            for (int c = 0; c < 4; c++) {
                int b = score_bucket(e[c]);
                if (b >= T) {
                    unsigned pos = g_base[b] + atomicAdd(&g_cnt[b], 1u);
                    if (pos < CAND_MAX) {
                        unsigned idx = (unsigned)(4 * i + c);
                        g_cand[pos] = ((unsigned long long)__float_as_uint(e[c]) << 32)
                                    | (unsigned long long)(0xFFFFFFFFu - idx);
                    }
                }
            }
        }
    }
}

// ---------------- K5: per-bucket micro bitonic sorts (descending) -----------
__global__ void bsort_k() {
    __shared__ unsigned long long s[BCAP];
    int T = g_thresh;
    int t = threadIdx.x;                           // 128 threads
    for (int b = T + blockIdx.x; b < HB; b += gridDim.x) {
        unsigned base = g_base[b];
        if (base >= (unsigned)NPRE) continue;      // never read
        unsigned cnt = g_cnt[b];
        if (cnt <= 1) continue;
        int m = (cnt < (unsigned)BCAP) ? (int)cnt : BCAP;
        int kmax = 2; while (kmax < m) kmax <<= 1; // sort region = pow2 >= m
        for (int i = t; i < kmax; i += 128) s[i] = (i < m) ? g_cand[base + i] : 0ull;
        __syncthreads();
        for (int k = 2; k <= kmax; k <<= 1) {
            for (int j = k >> 1; j > 0; j >>= 1) {
                for (int p = t; p < (kmax >> 1); p += 128) {
                    int i = ((p & ~(j - 1)) << 1) | (p & (j - 1));
                    int x = i | j;
                    unsigned long long a = s[i], bb = s[x];
                    bool desc = ((i & k) == 0);
                    if (desc ? (a < bb) : (a > bb)) { s[i] = bb; s[x] = a; }
                }
                __syncthreads();
            }
        }
        for (int i = t; i < m; i += 128) g_cand[base + i] = s[i];
        __syncthreads();
    }
}

// ---------------- K6: decode top NPRE boxes into SoA ------------------------
__global__ void decode_k(const float* __restrict__ enc,
                         const float* __restrict__ anch, int n) {
    int r = blockIdx.x * blockDim.x + threadIdx.x;
    if (r >= NROWS) return;
    float y1 = 0.f, x1 = 0.f, y2 = 0.f, x2 = 0.f, sc = 0.f;
    if (r < NPRE) {
        unsigned long long key = g_cand[r];
        unsigned idx = 0xFFFFFFFFu - (unsigned)(key & 0xFFFFFFFFull);
        if (idx < (unsigned)n) {
            sc = __uint_as_float((unsigned)(key >> 32));
            float4 a = ((const float4*)anch)[idx];   // [y1, x1, y2, x2]
            float4 e = ((const float4*)enc)[idx];    // [ty, tx, th, tw]
            float ha = a.z - a.x, wa = a.w - a.y;
            float cya = a.x + 0.5f * ha, cxa = a.y + 0.5f * wa;
            float cy = e.x * ha + cya;
            float cx = e.y * wa + cxa;
            float h  = expf(e.z) * ha;
            float w  = expf(e.w) * wa;
            y1 = cy - 0.5f * h; x1 = cx - 0.5f * w;
            y2 = cy + 0.5f * h; x2 = cx + 0.5f * w;
        }
    }
    g_y1[r] = y1; g_x1[r] = x1; g_y2[r] = y2; g_x2[r] = x2;
    g_pa[r] = 0.7f * (y2 - y1) * (x2 - x1);
    g_scores[r] = sc;
}

// ---------------- K7: IoU bitmask, transposed coalesced writes --------------
// iou > 0.7  <=>  1.7*inter > 0.7*areaA + 0.7*areaB
__global__ void mask_k(int col0) {
    if (*(volatile int*)&g_done) return;
    int bx = col0 + blockIdx.x;
    int by = blockIdx.y;
    if (bx >= NB || by > bx) return;

    __shared__ float4 colb[64];
    __shared__ float  colp[64];
    int t = threadIdx.x;
    int j = bx * 64 + t;
    colb[t] = make_float4(g_y1[j], g_x1[j], g_y2[j], g_x2[j]);
    colp[t] = g_pa[j];
    __syncthreads();

    int i = by * 64 + t;
    float y1 = g_y1[i], x1 = g_x1[i], y2 = g_y2[i], x2 = g_x2[i];
    float pa = g_pa[i];
    unsigned long long m = 0ull;

    if (bx > by) {
#pragma unroll 16
        for (int c = 0; c < 64; c++) {
            float4 cb = colb[c];
            float iy1 = fmaxf(y1, cb.x), ix1 = fmaxf(x1, cb.y);
            float iy2 = fminf(y2, cb.z), ix2 = fminf(x2, cb.w);
            float dy = fmaxf(iy2 - iy1, 0.f), dx = fmaxf(ix2 - ix1, 0.f);
            bool cond = fmaf(1.7f, dy * dx, -pa) > colp[c];
            m |= ((unsigned long long)cond) << c;
        }
    } else {  // diagonal block: only c > t
        for (int c = t + 1; c < 64; c++) {
            float4 cb = colb[c];
            float iy1 = fmaxf(y1, cb.x), ix1 = fmaxf(x1, cb.y);
            float iy2 = fminf(y2, cb.z), ix2 = fminf(x2, cb.w);
            float dy = fmaxf(iy2 - iy1, 0.f), dx = fmaxf(ix2 - ix1, 0.f);
            bool cond = fmaf(1.7f, dy * dx, -pa) > colp[c];
            m |= ((unsigned long long)cond) << c;
        }
    }
    g_maskT[bx][i] = m;   // coalesced across t
}

// ---------------- K8: NMS partial reduce (role-split pipelined) -------------
__global__ void nms_part_k(int g0, int g1) {
    if (*(volatile int*)&g_done) return;
    __shared__ int                s_kept[NPOST];
    __shared__ unsigned long long s_alive[NB];
    __shared__ unsigned long long s_col[64];
    __shared__ unsigned long long s_gnext[64];
    __shared__ unsigned long long s_crossbuf[2];
    __shared__ unsigned long long s_colOR;
    __shared__ unsigned long long s_alivew;
    __shared__ int s_kc;
    int t = threadIdx.x;                       // 256 threads
    int kcount = g_kcount;
    for (int i = t; i < kcount; i += 256) s_kept[i] = g_kept[i];
    for (int i = t; i < NB; i += 256) s_alive[i] = g_alive[i];
    if (t == 0) { s_crossbuf[0] = 0ull; s_crossbuf[1] = 0ull; s_colOR = 0ull; }
    __syncthreads();
    // prologue: cross for g0 over rows < g0*64 (alive only)
    {
        unsigned long long p = 0ull;
        for (int r = t; r < g0 * 64; r += 256)
            if ((s_alive[r >> 6] >> (r & 63)) & 1ull) p |= g_maskT[g0][r];
        if (p) atomicOr(&s_crossbuf[g0 & 1], p);
    }
    __syncthreads();

    if (g1 > NB) g1 = NB;
    for (int g = g0; g < g1; ++g) {
        int base = g * 64;
        int n = NPRE - base; if (n > 64) n = 64;
        int cur = g & 1, nxt = cur ^ 1;
        bool haveNext = (g + 1 < NB);
        // ---- Phase A (role split): current cols | next-col prefetch | next cross
        if (t < 64) {
            unsigned long long w = g_maskT[g][base + t];
            s_col[t] = w;
            if (w) atomicOr(&s_colOR, w);
        } else if (t < 128) {
            s_gnext[t - 64] = haveNext ? g_maskT[g + 1][base + (t - 64)] : 0ull;
        } else if (haveNext) {
            unsigned long long p = 0ull;
            for (int r = t - 128; r < base; r += 128)
                if ((s_alive[r >> 6] >> (r & 63)) & 1ull) p |= g_maskT[g + 1][r];
            if (p) atomicOr(&s_crossbuf[nxt], p);
        }
        __syncthreads();
        // ---- Phase B: decision
        unsigned long long cross = s_crossbuf[cur];
        unsigned long long colOR = s_colOR;
        unsigned long long rowmask = (n == 64) ? ~0ull : ((1ull << n) - 1ull);
        bool fast = (cross == 0ull && colOR == 0ull && kcount + n <= NPOST);
        if (fast) {
            if (t < n) s_kept[kcount + t] = base + t;
            if (t == 0) { s_kc = kcount + n; s_alivew = rowmask; }
        } else if (t == 0) {
            unsigned long long avail = (~cross) & rowmask;
            unsigned long long alivew = 0ull;
            int kc = kcount;
            while (avail && kc < NPOST) {
                int k1 = __ffsll((long long)avail) - 1;
                unsigned long long r = avail & (avail - 1);
                unsigned long long c1 = s_col[k1];
                int k2 = -1, k3 = -1, k4 = -1;
                unsigned long long c2 = 0, c3 = 0, c4 = 0;
                if (r) { k2 = __ffsll((long long)r) - 1; c2 = s_col[k2]; r &= r - 1;
                    if (r) { k3 = __ffsll((long long)r) - 1; c3 = s_col[k3]; r &= r - 1;
                        if (r) { k4 = __ffsll((long long)r) - 1; c4 = s_col[k4]; r &= r - 1; } } }
                unsigned long long m = c1;
                s_kept[kc++] = base + k1; alivew |= 1ull << k1;
                if (k2 >= 0 && kc < NPOST && !((m >> k2) & 1ull)) { s_kept[kc++] = base + k2; alivew |= 1ull << k2; m |= c2; }
                if (k3 >= 0 && kc < NPOST && !((m >> k3) & 1ull)) { s_kept[kc++] = base + k3; alivew |= 1ull << k3; m |= c3; }
                if (k4 >= 0 && kc < NPOST && !((m >> k4) & 1ull)) { s_kept[kc++] = base + k4; alivew |= 1ull << k4; m |= c4; }
                avail = r & ~m;
            }
            s_kc = kc; s_alivew = alivew;
        }
        __syncthreads();
        // ---- Phase C: combine + bookkeeping
        kcount = s_kc;
        unsigned long long aw = s_alivew;
        if (t < 64 && ((aw >> t) & 1ull)) {
            unsigned long long w = s_gnext[t];
            if (w) atomicOr(&s_crossbuf[nxt], w);
        }
        if (t == 0) { s_alive[g] = aw; s_crossbuf[cur] = 0ull; s_colOR = 0ull; }
        __syncthreads();
        if (kcount >= NPOST) break;
    }
    // epilogue
    int kc0 = g_kcount;
    for (int i = kc0 + t; i < kcount; i += 256) g_kept[i] = s_kept[i];
    for (int i = t; i < NB; i += 256) g_alive[i] = s_alive[i];
    if (t == 0) {
        g_kcount = kcount;
        if (kcount >= NPOST || g1 >= NB) g_done = 1;
    }
}

// ---------------- K9: write output ------------------------------------------
__global__ void out_k(float* __restrict__ out) {
    int kcount = g_kcount;
    int o = blockIdx.x * blockDim.x + threadIdx.x;
    if (o < NPOST) {
        if (o < kcount) {
            int i = g_kept[o];
            ((float4*)out)[o] = make_float4(g_y1[i], g_x1[i], g_y2[i], g_x2[i]);
            out[NPOST * 4 + o] = g_scores[i];
        } else {
            ((float4*)out)[o] = make_float4(0.f, 0.f, 0.f, 0.f);
            out[NPOST * 4 + o] = 0.f;
        }
    }
}

// ---------------- launch ----------------------------------------------------
extern "C" void kernel_launch(void* const* d_in, const int* in_sizes, int n_in,
                              void* d_out, int out_size) {
    const float* enc    = (const float*)d_in[0];  // encoded_bboxes [N,4]
    const float* anch   = (const float*)d_in[1];  // anchors        [N,4]
    const float* scores = (const float*)d_in[2];  // scores         [N]
    float* out = (float*)d_out;                   // 2000*4 boxes + 2000 scores
    int n = in_sizes[2];
    int n4 = n / 4;

    zero_k<<<(HB + 255) / 256, 256>>>();
    hist_stash_k<<<1024, 256>>>((const float4*)scores, n4);
    thresh_k<<<1, 1024>>>();
    compact_k<<<512, 256>>>((const float4*)scores, n4);
    bsort_k<<<128, 128>>>();
    decode_k<<<(NROWS + 127) / 128, 128>>>(enc, anch, n);

    // chunked mask+NMS with early-exit flag; expected exit ~group 33
    mask_k<<<dim3(36, 36), 64>>>(0);
    nms_part_k<<<1, 256>>>(0, 36);
    mask_k<<<dim3(24, 60), 64>>>(36);
    nms_part_k<<<1, 256>>>(36, 60);
    mask_k<<<dim3(34, 94), 64>>>(60);
    nms_part_k<<<1, 256>>>(60, 94);

    out_k<<<(NPOST + 255) / 256, 256>>>(out);
}